// round 10
// baseline (speedup 1.0000x reference)
#include <cuda_runtime.h>

#define NB  4
#define NPT 16384
#define NQ  1024
#define KK  20
#define KK1 21
#define NCELL 4096

#define NT   512                 // FPS threads per CTA
#define BPT  32                  // points per bucket (per thread)

// output layout (all f32, concatenated in reference return order)
#define OFF_IND 0
#define OFF_Q   (NB*NQ)                   // 4096
#define OFF_NM  (OFF_Q  + NB*NQ*3)        // 16384
#define OFF_DM  (OFF_NM + NB*NQ*KK)       // 98304
#define OFF_NO  (OFF_DM + NB*NQ*KK*3)     // 344064
#define OFF_DO  (OFF_NO + NB*NQ*KK)       // 425984

__device__ float    g_query[NB*NQ*3];   // sampled query coords
__device__ unsigned g_sidx[NB*NPT];     // sorted-pos -> original index

__device__ __forceinline__ unsigned morton4(unsigned cx, unsigned cy, unsigned cz)
{
    unsigned m = 0;
#pragma unroll
    for (int b = 0; b < 4; ++b)
        m |= (((cx >> b) & 1u) << (3 * b))
           | (((cy >> b) & 1u) << (3 * b + 1))
           | (((cz >> b) & 1u) << (3 * b + 2));
    return m;
}

__device__ __forceinline__ unsigned cellof(float x, float y, float z)
{
    unsigned cx = (unsigned)fminf(fmaxf((x + 4.0f) * 2.0f, 0.0f), 15.0f);
    unsigned cy = (unsigned)fminf(fmaxf((y + 4.0f) * 2.0f, 0.0f), 15.0f);
    unsigned cz = (unsigned)fminf(fmaxf((z + 4.0f) * 2.0f, 0.0f), 15.0f);
    return morton4(cx, cy, cz);
}

// ---------------------------------------------------------------------------
// Bucketed FPS, one CTA per batch, 512 threads x 32-point buckets.
// Halved warp count cuts the per-iteration fixed issue cost, barrier cost,
// and stage-2 payload vs the 1024-thread version; the doubled bucket scan
// only hits the few Morton-clustered touched warps. 128-reg budget keeps
// mind[32]+pk[16] spill-free.
// Distance = plain non-contracted left-to-right sum of squares (exact match
// to reference); argmax tie-break = first index (via max of inv = 0xFFFF^idx).
// ---------------------------------------------------------------------------
__global__ __launch_bounds__(NT, 1)
void fps_kernel(const float* __restrict__ pts, float* __restrict__ out)
{
    extern __shared__ float sm[];
    float*          sx   = sm;
    float*          sy   = sm + NPT;
    float*          sz   = sm + 2 * NPT;
    unsigned*       hist = (unsigned*)(sm + 3 * NPT);        // 16KB sort phase
    unsigned short* rank = (unsigned short*)(sm + 3 * NPT);  // 32KB after sort

    __shared__ unsigned long long s_part[2][16];
    __shared__ unsigned s_wsum[16];

    const int b    = blockIdx.x;
    const int tid  = threadIdx.x;
    const int lane = tid & 31, wid = tid >> 5;    // 16 warps
    const float* P = pts + (size_t)b * NPT * 3;
    unsigned* sidx = g_sidx + b * NPT;

    // ---- counting sort by Morton cell ----
#pragma unroll
    for (int k = 0; k < NCELL / NT; ++k) hist[tid + k * NT] = 0;
    __syncthreads();

#pragma unroll
    for (int k = 0; k < NPT / NT; ++k) {
        int i = tid + k * NT;
        float x = P[i * 3], y = P[i * 3 + 1], z = P[i * 3 + 2];
        atomicAdd(&hist[cellof(x, y, z)], 1u);
    }
    __syncthreads();

    // exclusive scan of hist[4096]: 8 cells per thread
    unsigned v[8], s = 0;
#pragma unroll
    for (int u = 0; u < 8; ++u) { v[u] = hist[8 * tid + u]; s += v[u]; }
    unsigned inc = s;
#pragma unroll
    for (int o = 1; o < 32; o <<= 1) {
        unsigned n = __shfl_up_sync(0xffffffffu, inc, o);
        if (lane >= o) inc += n;
    }
    if (lane == 31) s_wsum[wid] = inc;
    __syncthreads();
    if (tid < 16) {
        unsigned w = s_wsum[tid], wi = w;
#pragma unroll
        for (int o = 1; o < 16; o <<= 1) {
            unsigned n = __shfl_up_sync(0x0000FFFFu, wi, o);
            if (tid >= o) wi += n;
        }
        s_wsum[tid] = wi - w;   // exclusive warp base
    }
    __syncthreads();
    unsigned run = s_wsum[wid] + inc - s;
#pragma unroll
    for (int u = 0; u < 8; ++u) { hist[8 * tid + u] = run; run += v[u]; }
    __syncthreads();

    // scatter: sorted pos p -> smem slot (p%32)*512 + p/32
#pragma unroll
    for (int k = 0; k < NPT / NT; ++k) {
        int i = tid + k * NT;
        float x = P[i * 3], y = P[i * 3 + 1], z = P[i * 3 + 2];
        unsigned pos = atomicAdd(&hist[cellof(x, y, z)], 1u);
        int slot = (int)(pos & (BPT - 1)) * NT + (int)(pos / BPT);
        sx[slot] = x; sy[slot] = y; sz[slot] = z;
        sidx[pos] = (unsigned)i;
    }
    __syncthreads();   // scatter complete; hist region now dead

    // ---- rank table (overwrites hist region) ----
#pragma unroll
    for (int k = 0; k < NPT / NT; ++k) {
        int pos = tid + k * NT;
        rank[sidx[pos]] = (unsigned short)pos;
    }

    // ---- per-bucket state ----
    float    mind[BPT];
    unsigned pk[BPT / 2];
    float lox = 1e30f, loy = 1e30f, loz = 1e30f;
    float hix = -1e30f, hiy = -1e30f, hiz = -1e30f;
#pragma unroll
    for (int j = 0; j < BPT; ++j) {
        float x = sx[j * NT + tid];
        float y = sy[j * NT + tid];
        float z = sz[j * NT + tid];
        lox = fminf(lox, x); hix = fmaxf(hix, x);
        loy = fminf(loy, y); hiy = fmaxf(hiy, y);
        loz = fminf(loz, z); hiz = fmaxf(hiz, z);
        mind[j] = 1e10f;
        unsigned inv = 0xFFFFu ^ sidx[BPT * tid + j];
        if (j & 1) pk[j >> 1] |= inv << 16;
        else       pk[j >> 1]  = inv;
    }
    float bm = 1e10f;
    unsigned binv = 0;
#pragma unroll
    for (int j = 0; j < BPT; ++j) {
        unsigned inv = (j & 1) ? (pk[j >> 1] >> 16) : (pk[j >> 1] & 0xFFFFu);
        binv = inv > binv ? inv : binv;     // all mind equal -> max inv
    }
    __syncthreads();   // rank visible

    // first sample = original index 0 (broadcast LDG)
    float qx = P[0], qy = P[1], qz = P[2];
    if (tid == 0) {
        out[OFF_IND + b * NQ] = 0.0f;
        float* oq = out + OFF_Q + (size_t)b * NQ * 3;
        oq[0] = qx; oq[1] = qy; oq[2] = qz;
        float* gq = g_query + b * NQ * 3;
        gq[0] = qx; gq[1] = qy; gq[2] = qz;
    }

    // ---- main FPS loop: one barrier per iteration ----
    for (int it = 1; it < NQ; ++it) {
        float dx = fmaxf(fmaxf(lox - qx, qx - hix), 0.0f);
        float dy = fmaxf(fmaxf(loy - qy, qy - hiy), 0.0f);
        float dz = fmaxf(fmaxf(loz - qz, qz - hiz), 0.0f);
        float lb2 = dx * dx + dy * dy + dz * dz;
        if (lb2 * 0.999f < bm) {
            // lean distance-only rescan
            float nbm = 0.0f;
#pragma unroll
            for (int j = 0; j < BPT; ++j) {
                float t0 = sx[j * NT + tid] - qx;
                float t1 = sy[j * NT + tid] - qy;
                float t2 = sz[j * NT + tid] - qz;
                // plain (non-contracted) sum of squares, left-to-right
                float d = __fadd_rn(__fadd_rn(__fmul_rn(t0, t0),
                                              __fmul_rn(t1, t1)),
                                    __fmul_rn(t2, t2));
                float m = fminf(mind[j], d);
                mind[j] = m;
                nbm = fmaxf(nbm, m);
            }
            bm = nbm;
            // resolve tie-break index (max inv among mind == bm)
            unsigned nb = 0;
#pragma unroll
            for (int j = 0; j < BPT; ++j) {
                unsigned inv = (j & 1) ? (pk[j >> 1] >> 16)
                                       : (pk[j >> 1] & 0xFFFFu);
                if (mind[j] == bm && inv > nb) nb = inv;
            }
            binv = nb;
        }

        // stage 1: warp lexicographic argmax via redux
        unsigned bd   = __float_as_uint(bm);
        unsigned dmax = __reduce_max_sync(0xffffffffu, bd);
        unsigned imax = __reduce_max_sync(0xffffffffu,
                                          (bd == dmax) ? binv : 0u);
        const int p = it & 1;
        if (lane == 0)
            s_part[p][wid] = ((unsigned long long)dmax << 32) | imax;
        __syncthreads();

        // stage 2: every warp reduces the 16 partials (no 2nd barrier)
        unsigned long long v2 = (lane < 16) ? s_part[p][lane] : 0ULL;
        unsigned d2 = (unsigned)(v2 >> 32);
        unsigned i2 = (unsigned)v2;
        unsigned dW = __reduce_max_sync(0xffffffffu, d2);
        unsigned iW = __reduce_max_sync(0xffffffffu, (d2 == dW) ? i2 : 0u);
        unsigned g  = 0xFFFFu ^ iW;          // original index of winner

        int slot = rank[g];
        int addr = (slot & (BPT - 1)) * NT + (slot / BPT);
        qx = sx[addr]; qy = sy[addr]; qz = sz[addr];

        if (tid == 0) {
            out[OFF_IND + b * NQ + it] = (float)g;
            float* oq = out + OFF_Q + ((size_t)b * NQ + it) * 3;
            oq[0] = qx; oq[1] = qy; oq[2] = qz;
            float* gq = g_query + (b * NQ + it) * 3;
            gq[0] = qx; gq[1] = qy; gq[2] = qz;
        }
    }
}

// ---------------------------------------------------------------------------
// Merged KNN (Gmid + Gout, one launch): warp-per-query exact top-(K+1),
// ascending (dist, idx) keys. Candidate buffer + running 21st-best
// threshold; flush selection uses redux min pairs. Distance matches
// reference pdist2: (sq_q+sq_p) - 2*dot (FMA dot), clamped >= 0.
// ---------------------------------------------------------------------------
__device__ __forceinline__ unsigned long long u64min(unsigned long long a,
                                                     unsigned long long b)
{ return a < b ? a : b; }

__device__ __forceinline__ void knn_flush(unsigned long long& cand,
                                          unsigned long long& curT,
                                          int& cnt,
                                          unsigned long long* buf,
                                          int lane)
{
    __syncwarp(0xffffffffu);
    unsigned long long r0 = cand;
    unsigned long long r1 = (lane      < cnt) ? buf[lane]      : ~0ULL;
    unsigned long long r2 = (lane + 32 < cnt) ? buf[lane + 32] : ~0ULL;
    unsigned long long r3 = (lane + 64 < cnt) ? buf[lane + 64] : ~0ULL;
    unsigned long long nc = ~0ULL;
#pragma unroll
    for (int r = 0; r < KK1; ++r) {
        unsigned long long m = u64min(u64min(r0, r1), u64min(r2, r3));
        unsigned md = (unsigned)(m >> 32), mi = (unsigned)m;
        unsigned dmin = __reduce_min_sync(0xffffffffu, md);
        unsigned imin = __reduce_min_sync(0xffffffffu,
                                          (md == dmin) ? mi : 0xFFFFFFFFu);
        unsigned long long w = ((unsigned long long)dmin << 32) | imin;
        if (lane == r) nc = w;
        if (r0 == w) r0 = ~0ULL;
        else if (r1 == w) r1 = ~0ULL;
        else if (r2 == w) r2 = ~0ULL;
        else if (r3 == w) r3 = ~0ULL;
    }
    cand = nc;
    curT = __shfl_sync(0xffffffffu, nc, KK1 - 1);
    cnt  = 0;
    __syncwarp(0xffffffffu);
}

#define KNN_BLOCKS_MID ((NB * NQ) / 8)    // 512

__global__ __launch_bounds__(256)
void knn_kernel(const float* __restrict__ pts,
                float* __restrict__ outNbrM, float* __restrict__ outDM,
                float* __restrict__ outNbrO, float* __restrict__ outDO)
{
    __shared__ unsigned long long s_buf[8][96];
    const int warp = threadIdx.x >> 5;
    const int lane = threadIdx.x & 31;
    const int mode = (blockIdx.x < KNN_BLOCKS_MID) ? 0 : 1;
    const int blk  = mode ? (blockIdx.x - KNN_BLOCKS_MID) : blockIdx.x;
    const int wg   = blk * 8 + warp;             // 0..4095
    const int b    = wg >> 10;
    const int m    = wg & 1023;

    const float* Q = g_query + (b * NQ + m) * 3;
    float qx = Q[0], qy = Q[1], qz = Q[2];
    float sqq = __fadd_rn(__fadd_rn(__fmul_rn(qx, qx), __fmul_rn(qy, qy)),
                          __fmul_rn(qz, qz));

    const float* Pb = (mode == 0) ? (pts + (size_t)b * NPT * 3)
                                  : (g_query + b * NQ * 3);
    const int npts  = (mode == 0) ? NPT : NQ;
    float* outNbr   = (mode == 0) ? outNbrM : outNbrO;
    float* outD     = (mode == 0) ? outDM   : outDO;

    unsigned long long cand = ~0ULL, curT = ~0ULL;
    int cnt = 0;
    unsigned long long* buf = s_buf[warp];
    const unsigned ltmask = (1u << lane) - 1u;

    const int steps = npts >> 5;
    for (int j = 0; j < steps; j += 2) {
        int i0 = (j << 5) + lane;
        int i1 = i0 + 32;
        const float* p0 = Pb + i0 * 3;
        const float* p1 = Pb + i1 * 3;
        float ax = __ldg(p0), ay = __ldg(p0 + 1), az = __ldg(p0 + 2);
        float bx = __ldg(p1), by = __ldg(p1 + 1), bz = __ldg(p1 + 2);

        float sa = __fadd_rn(__fadd_rn(__fmul_rn(ax, ax), __fmul_rn(ay, ay)),
                             __fmul_rn(az, az));
        float da = __fmaf_rn(qz, az, __fmaf_rn(qy, ay, __fmul_rn(qx, ax)));
        float d0 = fmaxf(__fsub_rn(__fadd_rn(sqq, sa), __fmul_rn(2.0f, da)),
                         0.0f);
        float sb = __fadd_rn(__fadd_rn(__fmul_rn(bx, bx), __fmul_rn(by, by)),
                             __fmul_rn(bz, bz));
        float db = __fmaf_rn(qz, bz, __fmaf_rn(qy, by, __fmul_rn(qx, bx)));
        float d1 = fmaxf(__fsub_rn(__fadd_rn(sqq, sb), __fmul_rn(2.0f, db)),
                         0.0f);

        unsigned long long k0 =
            ((unsigned long long)__float_as_uint(d0) << 32) | (unsigned)i0;
        unsigned long long k1 =
            ((unsigned long long)__float_as_uint(d1) << 32) | (unsigned)i1;

        bool in0 = k0 < curT;
        unsigned b0 = __ballot_sync(0xffffffffu, in0);
        if (in0) buf[cnt + __popc(b0 & ltmask)] = k0;
        cnt += __popc(b0);

        bool in1 = k1 < curT;
        unsigned b1 = __ballot_sync(0xffffffffu, in1);
        if (in1) buf[cnt + __popc(b1 & ltmask)] = k1;
        cnt += __popc(b1);

        if (cnt >= 32) knn_flush(cand, curT, cnt, buf, lane);
    }
    if (cnt > 0) knn_flush(cand, curT, cnt, buf, lane);

    if (lane >= 1 && lane < KK1) {
        unsigned idx = (unsigned)(cand & 0xFFFFFFFFu);
        size_t o = (size_t)wg * KK + (lane - 1);
        outNbr[o] = (float)idx;
        const float* ps = Pb + idx * 3;
        outD[o * 3 + 0] = qx - ps[0];
        outD[o * 3 + 1] = qy - ps[1];
        outD[o * 3 + 2] = qz - ps[2];
    }
}

extern "C" void kernel_launch(void* const* d_in, const int* in_sizes, int n_in,
                              void* d_out, int out_size)
{
    const float* points = (const float*)d_in[0];
    float* out = (float*)d_out;

    const int fps_smem = 3 * NPT * (int)sizeof(float)
                       + NPT * (int)sizeof(unsigned short);   // 229376 B
    cudaFuncSetAttribute(fps_kernel,
                         cudaFuncAttributeMaxDynamicSharedMemorySize,
                         fps_smem);

    fps_kernel<<<NB, NT, fps_smem>>>(points, out);

    knn_kernel<<<2 * KNN_BLOCKS_MID, 256>>>(points,
                                            out + OFF_NM, out + OFF_DM,
                                            out + OFF_NO, out + OFF_DO);
}

// round 11
// speedup vs baseline: 1.1815x; 1.1815x over previous
#include <cuda_runtime.h>

#define NB  4
#define NPT 16384
#define NQ  1024
#define KK  20
#define KK1 21
#define NCELL 4096

// output layout (all f32, concatenated in reference return order)
#define OFF_IND 0
#define OFF_Q   (NB*NQ)                   // 4096
#define OFF_NM  (OFF_Q  + NB*NQ*3)        // 16384
#define OFF_DM  (OFF_NM + NB*NQ*KK)       // 98304
#define OFF_NO  (OFF_DM + NB*NQ*KK*3)     // 344064
#define OFF_DO  (OFF_NO + NB*NQ*KK)       // 425984

__device__ float    g_query[NB*NQ*3];   // sampled query coords
__device__ unsigned g_sidx[NB*NPT];     // sorted-pos -> original index

// ---------------- packed f32x2 helpers (per-half IEEE RN, exact) ----------
__device__ __forceinline__ unsigned long long pack2(float a, float b)
{ unsigned long long r; asm("mov.b64 %0, {%1, %2};" : "=l"(r) : "f"(a), "f"(b)); return r; }
__device__ __forceinline__ void unpack2(unsigned long long v, float& a, float& b)
{ asm("mov.b64 {%0, %1}, %2;" : "=f"(a), "=f"(b) : "l"(v)); }
__device__ __forceinline__ unsigned long long add2(unsigned long long a, unsigned long long b)
{ unsigned long long r; asm("add.rn.f32x2 %0, %1, %2;" : "=l"(r) : "l"(a), "l"(b)); return r; }
__device__ __forceinline__ unsigned long long mul2(unsigned long long a, unsigned long long b)
{ unsigned long long r; asm("mul.rn.f32x2 %0, %1, %2;" : "=l"(r) : "l"(a), "l"(b)); return r; }

__device__ __forceinline__ unsigned morton4(unsigned cx, unsigned cy, unsigned cz)
{
    unsigned m = 0;
#pragma unroll
    for (int b = 0; b < 4; ++b)
        m |= (((cx >> b) & 1u) << (3 * b))
           | (((cy >> b) & 1u) << (3 * b + 1))
           | (((cz >> b) & 1u) << (3 * b + 2));
    return m;
}

__device__ __forceinline__ unsigned cellof(float x, float y, float z)
{
    unsigned cx = (unsigned)fminf(fmaxf((x + 4.0f) * 2.0f, 0.0f), 15.0f);
    unsigned cy = (unsigned)fminf(fmaxf((y + 4.0f) * 2.0f, 0.0f), 15.0f);
    unsigned cz = (unsigned)fminf(fmaxf((z + 4.0f) * 2.0f, 0.0f), 15.0f);
    return morton4(cx, cy, cz);
}

// ---------------------------------------------------------------------------
// Bucketed FPS, one CTA per batch, 1024 threads x 16-pt buckets (the 916us
// R6 configuration) with ONE change: the touched-warp rescan runs in packed
// f32x2 (pair-layout smem, LDS.64 + add/mul.rn.f32x2 — per-half IEEE RN,
// bit-identical to the reference's non-contracted scalar form), roughly
// halving the scan issue cost. Winner payload = (inv<<16 | float_slot),
// which also removes the rank table and shortens the post-barrier chain.
// Tie-break: reference argmax (first/smallest original index) via max inv.
// ---------------------------------------------------------------------------
__global__ __launch_bounds__(1024, 1)
void fps_kernel(const float* __restrict__ pts, float* __restrict__ out)
{
    extern __shared__ float sm[];
    float*    sxf  = sm;                       // pair layout, see below
    float*    syf  = sm + NPT;
    float*    szf  = sm + 2 * NPT;
    unsigned* hist = (unsigned*)(sm + 3 * NPT);   // 16KB, sort phase only
    const unsigned long long* sxq = (const unsigned long long*)sxf;
    const unsigned long long* syq = (const unsigned long long*)syf;
    const unsigned long long* szq = (const unsigned long long*)szf;

    __shared__ unsigned long long s_part[2][32];
    __shared__ unsigned s_wsum[32];

    const int b    = blockIdx.x;
    const int tid  = threadIdx.x;
    const int lane = tid & 31, wid = tid >> 5;
    const float* P = pts + (size_t)b * NPT * 3;
    unsigned* sidx = g_sidx + b * NPT;

    // ---- counting sort by Morton cell ----
#pragma unroll
    for (int k = 0; k < 4; ++k) hist[tid + k * 1024] = 0;
    __syncthreads();

#pragma unroll
    for (int k = 0; k < 16; ++k) {
        int i = tid + k * 1024;
        float x = P[i * 3], y = P[i * 3 + 1], z = P[i * 3 + 2];
        atomicAdd(&hist[cellof(x, y, z)], 1u);
    }
    __syncthreads();

    // exclusive scan of hist[4096] in place
    unsigned v0 = hist[4 * tid], v1 = hist[4 * tid + 1];
    unsigned v2 = hist[4 * tid + 2], v3 = hist[4 * tid + 3];
    unsigned s = v0 + v1 + v2 + v3;
    unsigned inc = s;
#pragma unroll
    for (int o = 1; o < 32; o <<= 1) {
        unsigned n = __shfl_up_sync(0xffffffffu, inc, o);
        if (lane >= o) inc += n;
    }
    if (lane == 31) s_wsum[wid] = inc;
    __syncthreads();
    if (tid < 32) {
        unsigned w = s_wsum[tid], wi = w;
#pragma unroll
        for (int o = 1; o < 32; o <<= 1) {
            unsigned n = __shfl_up_sync(0xffffffffu, wi, o);
            if (tid >= o) wi += n;
        }
        s_wsum[tid] = wi - w;   // exclusive warp base
    }
    __syncthreads();
    unsigned base = s_wsum[wid] + inc - s;
    hist[4 * tid]     = base;
    hist[4 * tid + 1] = base + v0;
    hist[4 * tid + 2] = base + v0 + v1;
    hist[4 * tid + 3] = base + v0 + v1 + v2;
    __syncthreads();

    // scatter: sorted pos p (bucket t=p>>4, j=p&15) -> pair-layout float slot
    //   fs = (j>>1)*2048 + (t<<1) + (j&1)
    // so bucket t's points (2j2, 2j2+1) sit in one 8-byte word at dword
    // index j2*1024 + t (conflict-free LDS.64 across the warp).
#pragma unroll
    for (int k = 0; k < 16; ++k) {
        int i = tid + k * 1024;
        float x = P[i * 3], y = P[i * 3 + 1], z = P[i * 3 + 2];
        unsigned pos = atomicAdd(&hist[cellof(x, y, z)], 1u);
        int t = (int)(pos >> 4), j = (int)(pos & 15u);
        int fs = (j >> 1) * 2048 + (t << 1) + (j & 1);
        sxf[fs] = x; syf[fs] = y; szf[fs] = z;
        sidx[pos] = (unsigned)i;
    }
    __syncthreads();

    // ---- per-bucket state ----
    float    mind[16];
    unsigned pk[8];
    float lox = 1e30f, loy = 1e30f, loz = 1e30f;
    float hix = -1e30f, hiy = -1e30f, hiz = -1e30f;
#pragma unroll
    for (int j = 0; j < 16; ++j) {
        int fs = (j >> 1) * 2048 + (tid << 1) + (j & 1);
        float x = sxf[fs], y = syf[fs], z = szf[fs];
        lox = fminf(lox, x); hix = fmaxf(hix, x);
        loy = fminf(loy, y); hiy = fmaxf(hiy, y);
        loz = fminf(loz, z); hiz = fmaxf(hiz, z);
        mind[j] = 1e10f;
        unsigned inv = 0xFFFFu ^ sidx[16 * tid + j];
        if (j & 1) pk[j >> 1] |= inv << 16;
        else       pk[j >> 1]  = inv;
    }
    float bm = 1e10f;
    unsigned bpk = 0;
#pragma unroll
    for (int j = 0; j < 16; ++j) {
        unsigned inv = (j & 1) ? (pk[j >> 1] >> 16) : (pk[j >> 1] & 0xFFFFu);
        unsigned val = (inv << 16) |
            (unsigned)((j >> 1) * 2048 + (tid << 1) + (j & 1));
        bpk = val > bpk ? val : bpk;    // all mind equal -> max inv
    }

    // first sample = original index 0 (broadcast LDG)
    float qx = P[0], qy = P[1], qz = P[2];
    if (tid == 0) {
        out[OFF_IND + b * NQ] = 0.0f;
        float* oq = out + OFF_Q + (size_t)b * NQ * 3;
        oq[0] = qx; oq[1] = qy; oq[2] = qz;
        float* gq = g_query + b * NQ * 3;
        gq[0] = qx; gq[1] = qy; gq[2] = qz;
    }
    __syncthreads();

    // ---- main FPS loop: one barrier per iteration ----
    for (int it = 1; it < NQ; ++it) {
        float dx = fmaxf(fmaxf(lox - qx, qx - hix), 0.0f);
        float dy = fmaxf(fmaxf(loy - qy, qy - hiy), 0.0f);
        float dz = fmaxf(fmaxf(loz - qz, qz - hiz), 0.0f);
        float lb2 = dx * dx + dy * dy + dz * dz;
        if (lb2 * 0.999f < bm) {
            // packed f32x2 rescan: 2 points per step, exact per-half RN
            unsigned long long nqx = pack2(-qx, -qx);
            unsigned long long nqy = pack2(-qy, -qy);
            unsigned long long nqz = pack2(-qz, -qz);
            float nbm = 0.0f;
#pragma unroll
            for (int j2 = 0; j2 < 8; ++j2) {
                unsigned long long xv = sxq[j2 * 1024 + tid];
                unsigned long long yv = syq[j2 * 1024 + tid];
                unsigned long long zv = szq[j2 * 1024 + tid];
                unsigned long long tx = add2(xv, nqx);   // x - qx (exact)
                unsigned long long ty = add2(yv, nqy);
                unsigned long long tz = add2(zv, nqz);
                // plain non-contracted sum of squares, left-to-right
                unsigned long long dd =
                    add2(add2(mul2(tx, tx), mul2(ty, ty)), mul2(tz, tz));
                float dlo, dhi;
                unpack2(dd, dlo, dhi);
                float m0 = fminf(mind[2 * j2],     dlo);
                float m1 = fminf(mind[2 * j2 + 1], dhi);
                mind[2 * j2]     = m0;
                mind[2 * j2 + 1] = m1;
                nbm = fmaxf(nbm, fmaxf(m0, m1));
            }
            bm = nbm;
            // resolve winner payload (max inv among mind == bm)
            unsigned nb = 0;
#pragma unroll
            for (int j = 0; j < 16; ++j) {
                if (mind[j] == bm) {
                    unsigned inv = (j & 1) ? (pk[j >> 1] >> 16)
                                           : (pk[j >> 1] & 0xFFFFu);
                    unsigned val = (inv << 16) |
                        (unsigned)((j >> 1) * 2048 + (tid << 1) + (j & 1));
                    nb = val > nb ? val : nb;
                }
            }
            bpk = nb;
        }

        // stage 1: warp lexicographic argmax via redux
        unsigned bd   = __float_as_uint(bm);
        unsigned dmax = __reduce_max_sync(0xffffffffu, bd);
        unsigned imax = __reduce_max_sync(0xffffffffu, (bd == dmax) ? bpk : 0u);
        const int p = it & 1;
        if (lane == 0)
            s_part[p][wid] = ((unsigned long long)dmax << 32) | imax;
        __syncthreads();

        // stage 2: every warp reduces the 32 partials (no 2nd barrier)
        unsigned long long v = s_part[p][lane];
        unsigned d2 = (unsigned)(v >> 32);
        unsigned i2 = (unsigned)v;
        unsigned dW = __reduce_max_sync(0xffffffffu, d2);
        unsigned iW = __reduce_max_sync(0xffffffffu, (d2 == dW) ? i2 : 0u);
        unsigned slot = iW & 0xFFFFu;        // winner's float slot
        unsigned g    = 0xFFFFu ^ (iW >> 16);

        qx = sxf[slot]; qy = syf[slot]; qz = szf[slot];

        if (tid == 0) {
            out[OFF_IND + b * NQ + it] = (float)g;
            float* oq = out + OFF_Q + ((size_t)b * NQ + it) * 3;
            oq[0] = qx; oq[1] = qy; oq[2] = qz;
            float* gq = g_query + (b * NQ + it) * 3;
            gq[0] = qx; gq[1] = qy; gq[2] = qz;
        }
    }
}

// ---------------------------------------------------------------------------
// Merged KNN (Gmid + Gout, one launch): warp-per-query exact top-(K+1),
// ascending (dist, idx) keys. Candidate buffer + running 21st-best
// threshold; flush selection uses redux min pairs. Distance matches
// reference pdist2: (sq_q+sq_p) - 2*dot (FMA dot), clamped >= 0.
// ---------------------------------------------------------------------------
__device__ __forceinline__ unsigned long long u64min(unsigned long long a,
                                                     unsigned long long b)
{ return a < b ? a : b; }

__device__ __forceinline__ void knn_flush(unsigned long long& cand,
                                          unsigned long long& curT,
                                          int& cnt,
                                          unsigned long long* buf,
                                          int lane)
{
    __syncwarp(0xffffffffu);
    unsigned long long r0 = cand;
    unsigned long long r1 = (lane      < cnt) ? buf[lane]      : ~0ULL;
    unsigned long long r2 = (lane + 32 < cnt) ? buf[lane + 32] : ~0ULL;
    unsigned long long r3 = (lane + 64 < cnt) ? buf[lane + 64] : ~0ULL;
    unsigned long long nc = ~0ULL;
#pragma unroll
    for (int r = 0; r < KK1; ++r) {
        unsigned long long m = u64min(u64min(r0, r1), u64min(r2, r3));
        unsigned md = (unsigned)(m >> 32), mi = (unsigned)m;
        unsigned dmin = __reduce_min_sync(0xffffffffu, md);
        unsigned imin = __reduce_min_sync(0xffffffffu,
                                          (md == dmin) ? mi : 0xFFFFFFFFu);
        unsigned long long w = ((unsigned long long)dmin << 32) | imin;
        if (lane == r) nc = w;
        if (r0 == w) r0 = ~0ULL;
        else if (r1 == w) r1 = ~0ULL;
        else if (r2 == w) r2 = ~0ULL;
        else if (r3 == w) r3 = ~0ULL;
    }
    cand = nc;
    curT = __shfl_sync(0xffffffffu, nc, KK1 - 1);
    cnt  = 0;
    __syncwarp(0xffffffffu);
}

#define KNN_BLOCKS_MID ((NB * NQ) / 8)    // 512

__global__ __launch_bounds__(256)
void knn_kernel(const float* __restrict__ pts,
                float* __restrict__ outNbrM, float* __restrict__ outDM,
                float* __restrict__ outNbrO, float* __restrict__ outDO)
{
    __shared__ unsigned long long s_buf[8][96];
    const int warp = threadIdx.x >> 5;
    const int lane = threadIdx.x & 31;
    const int mode = (blockIdx.x < KNN_BLOCKS_MID) ? 0 : 1;
    const int blk  = mode ? (blockIdx.x - KNN_BLOCKS_MID) : blockIdx.x;
    const int wg   = blk * 8 + warp;             // 0..4095
    const int b    = wg >> 10;
    const int m    = wg & 1023;

    const float* Q = g_query + (b * NQ + m) * 3;
    float qx = Q[0], qy = Q[1], qz = Q[2];
    float sqq = __fadd_rn(__fadd_rn(__fmul_rn(qx, qx), __fmul_rn(qy, qy)),
                          __fmul_rn(qz, qz));

    const float* Pb = (mode == 0) ? (pts + (size_t)b * NPT * 3)
                                  : (g_query + b * NQ * 3);
    const int npts  = (mode == 0) ? NPT : NQ;
    float* outNbr   = (mode == 0) ? outNbrM : outNbrO;
    float* outD     = (mode == 0) ? outDM   : outDO;

    unsigned long long cand = ~0ULL, curT = ~0ULL;
    int cnt = 0;
    unsigned long long* buf = s_buf[warp];
    const unsigned ltmask = (1u << lane) - 1u;

    const int steps = npts >> 5;
    for (int j = 0; j < steps; j += 2) {
        int i0 = (j << 5) + lane;
        int i1 = i0 + 32;
        const float* p0 = Pb + i0 * 3;
        const float* p1 = Pb + i1 * 3;
        float ax = __ldg(p0), ay = __ldg(p0 + 1), az = __ldg(p0 + 2);
        float bx = __ldg(p1), by = __ldg(p1 + 1), bz = __ldg(p1 + 2);

        float sa = __fadd_rn(__fadd_rn(__fmul_rn(ax, ax), __fmul_rn(ay, ay)),
                             __fmul_rn(az, az));
        float da = __fmaf_rn(qz, az, __fmaf_rn(qy, ay, __fmul_rn(qx, ax)));
        float d0 = fmaxf(__fsub_rn(__fadd_rn(sqq, sa), __fmul_rn(2.0f, da)),
                         0.0f);
        float sb = __fadd_rn(__fadd_rn(__fmul_rn(bx, bx), __fmul_rn(by, by)),
                             __fmul_rn(bz, bz));
        float db = __fmaf_rn(qz, bz, __fmaf_rn(qy, by, __fmul_rn(qx, bx)));
        float d1 = fmaxf(__fsub_rn(__fadd_rn(sqq, sb), __fmul_rn(2.0f, db)),
                         0.0f);

        unsigned long long k0 =
            ((unsigned long long)__float_as_uint(d0) << 32) | (unsigned)i0;
        unsigned long long k1 =
            ((unsigned long long)__float_as_uint(d1) << 32) | (unsigned)i1;

        bool in0 = k0 < curT;
        unsigned b0 = __ballot_sync(0xffffffffu, in0);
        if (in0) buf[cnt + __popc(b0 & ltmask)] = k0;
        cnt += __popc(b0);

        bool in1 = k1 < curT;
        unsigned b1 = __ballot_sync(0xffffffffu, in1);
        if (in1) buf[cnt + __popc(b1 & ltmask)] = k1;
        cnt += __popc(b1);

        if (cnt >= 32) knn_flush(cand, curT, cnt, buf, lane);
    }
    if (cnt > 0) knn_flush(cand, curT, cnt, buf, lane);

    if (lane >= 1 && lane < KK1) {
        unsigned idx = (unsigned)(cand & 0xFFFFFFFFu);
        size_t o = (size_t)wg * KK + (lane - 1);
        outNbr[o] = (float)idx;
        const float* ps = Pb + idx * 3;
        outD[o * 3 + 0] = qx - ps[0];
        outD[o * 3 + 1] = qy - ps[1];
        outD[o * 3 + 2] = qz - ps[2];
    }
}

extern "C" void kernel_launch(void* const* d_in, const int* in_sizes, int n_in,
                              void* d_out, int out_size)
{
    const float* points = (const float*)d_in[0];
    float* out = (float*)d_out;

    const int fps_smem = 3 * NPT * (int)sizeof(float)
                       + NCELL * (int)sizeof(unsigned);   // 212992 B
    cudaFuncSetAttribute(fps_kernel,
                         cudaFuncAttributeMaxDynamicSharedMemorySize,
                         fps_smem);

    fps_kernel<<<NB, 1024, fps_smem>>>(points, out);

    knn_kernel<<<2 * KNN_BLOCKS_MID, 256>>>(points,
                                            out + OFF_NM, out + OFF_DM,
                                            out + OFF_NO, out + OFF_DO);
}